// round 6
// baseline (speedup 1.0000x reference)
#include <cuda_runtime.h>
#include <cuda_bf16.h>
#include <math.h>
#include <stdint.h>

#define NN 2000
#define BB 64
#define EMBED 512
#define LABELS 20
#define NC 31            // Taylor degree 30

#define MT 128           // gemm0 M tile
#define NMT 16
#define SPLIT0 9
#define SPLEN0 224
#define G0_BLOCKS (NMT * SPLIT0)   // 144

// smem tile layout (bf16, rows padded to 72 elements = 144B)
#define A_PAD 72
#define OFF_ALO 18432
#define OFF_BHI 36864
#define OFF_BLO 46080
#define BUF_STRIDE 55296
#define DSMEM (2 * BUF_STRIDE)

// ---- scratch (zero-initialized at module load; accumulators restored to 0
//      by their single consumer each invocation -> replay-safe) ----
__device__ float g_XT[NN * BB];
__device__ float g_mixedT[NN * BB];
__device__ float g_preact[NN * BB];    // gemm0 REDG accumulator
__device__ float g_hpre[EMBED * BB];   // gemm1 REDG accumulator
__device__ float g_hT[EMBED * BB];
__device__ float g_cn[NC][BB];
__device__ float g_cd[NC][BB];
__device__ float g_alpha, g_gamma;

__device__ __forceinline__ void mma16816(float* d, const uint32_t* a, const uint32_t* b) {
    asm volatile(
        "mma.sync.aligned.m16n8k16.row.col.f32.bf16.bf16.f32 "
        "{%0,%1,%2,%3}, {%4,%5,%6,%7}, {%8,%9}, {%0,%1,%2,%3};\n"
        : "+f"(d[0]), "+f"(d[1]), "+f"(d[2]), "+f"(d[3])
        : "r"(a[0]), "r"(a[1]), "r"(a[2]), "r"(a[3]), "r"(b[0]), "r"(b[1]));
}

// float4 -> bf16 hi + bf16 lo, stored at byte offset (8-aligned)
__device__ __forceinline__ void split_store(char* hi, char* lo, int byte, float4 v) {
    __nv_bfloat16 hx = __float2bfloat16(v.x), hy = __float2bfloat16(v.y);
    __nv_bfloat16 hz = __float2bfloat16(v.z), hw = __float2bfloat16(v.w);
    float lx = v.x - __bfloat162float(hx), ly = v.y - __bfloat162float(hy);
    float lz = v.z - __bfloat162float(hz), lw = v.w - __bfloat162float(hw);
    uint2 h2, l2;
    h2.x = (unsigned)__bfloat16_as_ushort(hx) | ((unsigned)__bfloat16_as_ushort(hy) << 16);
    h2.y = (unsigned)__bfloat16_as_ushort(hz) | ((unsigned)__bfloat16_as_ushort(hw) << 16);
    __nv_bfloat16 ax = __float2bfloat16(lx), ay = __float2bfloat16(ly);
    __nv_bfloat16 az = __float2bfloat16(lz), aw = __float2bfloat16(lw);
    l2.x = (unsigned)__bfloat16_as_ushort(ax) | ((unsigned)__bfloat16_as_ushort(ay) << 16);
    l2.y = (unsigned)__bfloat16_as_ushort(az) | ((unsigned)__bfloat16_as_ushort(aw) << 16);
    *(uint2*)(hi + byte) = h2;
    *(uint2*)(lo + byte) = l2;
}

// ============================================================================
// Fused: mma.sync bf16-split gemm0 (blocks 0..143, REDG epilogue)
//        + moments (144..207) + transpose (208..333)
// ============================================================================
__global__ __launch_bounds__(256, 1)
void k_main(const float* __restrict__ IG, const float* __restrict__ feat,
            const float* __restrict__ tw, const float* __restrict__ tb,
            const float* __restrict__ pw) {
    extern __shared__ __align__(16) char dsm[];
    const int bid = blockIdx.x;
    const int tid = threadIdx.x;

    if (bid < G0_BLOCKS) {
        const int wid = tid >> 5, lane = tid & 31;
        const int mt = bid & 15, sp = bid >> 4;
        const int rb = mt * MT;
        const int kb = sp * SPLEN0;
        int ke = kb + SPLEN0; if (ke > NN) ke = NN;
        const int nc = (ke - kb + 63) >> 6;

        const int warp_m = wid >> 1;
        const int warp_n = wid & 1;
        const int g = lane >> 2, tig = lane & 3;

        const int ar = tid >> 1, hh = tid & 1;
        const int brr = tid >> 2, qq = tid & 3;
        const bool rok = (rb + ar) < NN;
        const float* arow = IG + (size_t)(rb + ar) * NN;
        const float* brow = feat + (size_t)brr * NN;

        float acc[2][4][4];
#pragma unroll
        for (int t = 0; t < 2; t++)
#pragma unroll
            for (int u = 0; u < 4; u++)
#pragma unroll
                for (int j = 0; j < 4; j++) acc[t][u][j] = 0.f;

        float4 ra[8], rb4[4];
        auto ldg_chunk = [&](int c) {
            int m0 = kb + c * 64;
            int mlen = ke - m0; if (mlen > 64) mlen = 64;
#pragma unroll
            for (int i = 0; i < 8; i++) {
                int kk = hh * 32 + i * 4;
                float4 v = make_float4(0.f, 0.f, 0.f, 0.f);
                if (rok) {
                    if (kk + 4 <= mlen) v = *(const float4*)(arow + m0 + kk);
                    else if (kk < mlen) {
                        float* pv = &v.x;
#pragma unroll
                        for (int j = 0; j < 4; j++)
                            if (kk + j < mlen) pv[j] = arow[m0 + kk + j];
                    }
                }
                ra[i] = v;
            }
#pragma unroll
            for (int i = 0; i < 4; i++) {
                int kk = qq * 16 + i * 4;
                float4 v = make_float4(0.f, 0.f, 0.f, 0.f);
                if (kk + 4 <= mlen) v = *(const float4*)(brow + m0 + kk);
                else if (kk < mlen) {
                    float* pv = &v.x;
#pragma unroll
                    for (int j = 0; j < 4; j++)
                        if (kk + j < mlen) pv[j] = brow[m0 + kk + j];
                }
                rb4[i] = v;
            }
        };
        auto cvt_store = [&](int p) {
            char* base = dsm + p * BUF_STRIDE;
            char* Ahi = base;            char* Alo = base + OFF_ALO;
            char* Bhi = base + OFF_BHI;  char* Blo = base + OFF_BLO;
#pragma unroll
            for (int i = 0; i < 8; i++) {
                int kk = hh * 32 + i * 4;
                split_store(Ahi, Alo, ar * (A_PAD * 2) + kk * 2, ra[i]);
            }
#pragma unroll
            for (int i = 0; i < 4; i++) {
                int kk = qq * 16 + i * 4;
                split_store(Bhi, Blo, brr * (A_PAD * 2) + kk * 2, rb4[i]);
            }
        };
        auto compute = [&](int p) {
            char* base = dsm + p * BUF_STRIDE;
            char* Ahi = base;            char* Alo = base + OFF_ALO;
            char* Bhi = base + OFF_BHI;  char* Blo = base + OFF_BLO;
#pragma unroll
            for (int ks = 0; ks < 4; ks++) {
                const int ko = ks * 16;
                uint32_t ah[2][4], al[2][4], bh[4][2], bl[4][2];
#pragma unroll
                for (int t = 0; t < 2; t++) {
                    int row = warp_m * 32 + t * 16 + g;
                    int o0 = row * (A_PAD * 2) + (ko + tig * 2) * 2;
                    int o1 = (row + 8) * (A_PAD * 2) + (ko + tig * 2) * 2;
                    ah[t][0] = *(uint32_t*)(Ahi + o0);
                    ah[t][1] = *(uint32_t*)(Ahi + o1);
                    ah[t][2] = *(uint32_t*)(Ahi + o0 + 16);
                    ah[t][3] = *(uint32_t*)(Ahi + o1 + 16);
                    al[t][0] = *(uint32_t*)(Alo + o0);
                    al[t][1] = *(uint32_t*)(Alo + o1);
                    al[t][2] = *(uint32_t*)(Alo + o0 + 16);
                    al[t][3] = *(uint32_t*)(Alo + o1 + 16);
                }
#pragma unroll
                for (int u = 0; u < 4; u++) {
                    int col = warp_n * 32 + u * 8 + g;
                    int o = col * (A_PAD * 2) + (ko + tig * 2) * 2;
                    bh[u][0] = *(uint32_t*)(Bhi + o);
                    bh[u][1] = *(uint32_t*)(Bhi + o + 16);
                    bl[u][0] = *(uint32_t*)(Blo + o);
                    bl[u][1] = *(uint32_t*)(Blo + o + 16);
                }
#pragma unroll
                for (int t = 0; t < 2; t++)
#pragma unroll
                    for (int u = 0; u < 4; u++) {
                        mma16816(acc[t][u], ah[t], bh[u]);
                        mma16816(acc[t][u], ah[t], bl[u]);
                        mma16816(acc[t][u], al[t], bh[u]);
                    }
            }
        };

        ldg_chunk(0);
        for (int c = 0; c < nc; c++) {
            int p = c & 1;
            cvt_store(p);
            if (c + 1 < nc) ldg_chunk(c + 1);
            __syncthreads();
            compute(p);
        }

        // epilogue: REDG accumulate into g_preact (no partial buffers)
#pragma unroll
        for (int t = 0; t < 2; t++) {
            int r0 = rb + warp_m * 32 + t * 16 + g;
#pragma unroll
            for (int u = 0; u < 4; u++) {
                int cn = warp_n * 32 + u * 8 + tig * 2;
                if (r0 < NN) {
                    atomicAdd(&g_preact[(size_t)r0 * BB + cn], acc[t][u][0]);
                    atomicAdd(&g_preact[(size_t)r0 * BB + cn + 1], acc[t][u][1]);
                }
                if (r0 + 8 < NN) {
                    atomicAdd(&g_preact[(size_t)(r0 + 8) * BB + cn], acc[t][u][2]);
                    atomicAdd(&g_preact[(size_t)(r0 + 8) * BB + cn + 1], acc[t][u][3]);
                }
            }
        }
        return;
    }

    const int pid = bid - G0_BLOCKS;
    if (pid < 64) {
        // ---------------- moments (+ alpha/gamma on pid==0) ----------------
        if (pid == 0) {
            __shared__ float sa[64], sg[64];
            if (tid < 64) {
                sa[tid] = tw[tid] * pw[tid];
                sg[tid] = tb[tid] * pw[tid];
            }
            __syncthreads();
            if (tid == 0) {
                float A = 0.f, G = 0.f;
                for (int i = 0; i < 64; i++) { A += sa[i]; G += sg[i]; }
                g_alpha = A; g_gamma = G;
            }
            __syncthreads();
        }
        int b = pid;
        const float* xr = feat + b * NN;
        float acc[32];
#pragma unroll
        for (int k = 0; k < 32; k++) acc[k] = 0.f;
        for (int m = tid; m < NN; m += 256) {
            float v = xr[m];
            float pw2 = 1.f;
#pragma unroll
            for (int k = 0; k < 32; k++) { acc[k] += pw2; pw2 *= v; }
        }
#pragma unroll
        for (int k = 0; k < 32; k++) {
#pragma unroll
            for (int off = 16; off > 0; off >>= 1)
                acc[k] += __shfl_down_sync(0xffffffffu, acc[k], off);
        }
        __shared__ float red[32][8];
        __shared__ float sM[32];
        int lane = tid & 31, warp = tid >> 5;
        if (lane == 0) {
#pragma unroll
            for (int k = 0; k < 32; k++) red[k][warp] = acc[k];
        }
        __syncthreads();
        if (tid < 32) {
            float s = 0.f;
            for (int w = 0; w < 8; w++) s += red[tid][w];
            sM[tid] = s;
        }
        __syncthreads();
        if (tid < NC) {
            int k = tid;
            float fact = 1.f;
            for (int i = 2; i <= k; i++) fact *= (float)i;
            g_cd[k][b] = sM[k] / fact;
            g_cn[k][b] = sM[k + 1] / fact;
        }
    } else {
        // ---------------- transpose tile ----------------
        int t = pid - 64;                  // 0..125
        int m0 = (t % 63) * 32, b0 = (t / 63) * 32;
        __shared__ float tt[32][33];
        int x = tid & 31, y = tid >> 5;
#pragma unroll
        for (int j = 0; j < 32; j += 8) {
            int b = b0 + y + j, m = m0 + x;
            tt[y + j][x] = (m < NN) ? feat[b * NN + m] : 0.f;
        }
        __syncthreads();
#pragma unroll
        for (int j = 0; j < 32; j += 8) {
            int m = m0 + y + j, b = b0 + x;
            if (m < NN) g_XT[m * BB + b] = tt[x][y + j];
        }
    }
}

// preact + exact softmax term g(s) + relu + residual -> mixedT; re-zero preact
__global__ __launch_bounds__(256) void k_mix() {
    int idx4 = (blockIdx.x * 256 + threadIdx.x) * 4;   // 125*256*4 == NN*BB
    int b0 = idx4 & 63;                                // aligned to 4
    float4 pre = *(float4*)(g_preact + idx4);
    float4 x4 = *(float4*)(g_XT + idx4);
    float4 s4;
    s4.x = g_alpha * x4.x + g_gamma; s4.y = g_alpha * x4.y + g_gamma;
    s4.z = g_alpha * x4.z + g_gamma; s4.w = g_alpha * x4.w + g_gamma;
    float4 P = *(float4*)&g_cn[NC - 1][b0];
    float4 Q = *(float4*)&g_cd[NC - 1][b0];
#pragma unroll
    for (int k = NC - 2; k >= 0; k--) {
        float4 cn = *(float4*)&g_cn[k][b0];
        float4 cd = *(float4*)&g_cd[k][b0];
        P.x = P.x * s4.x + cn.x; Q.x = Q.x * s4.x + cd.x;
        P.y = P.y * s4.y + cn.y; Q.y = Q.y * s4.y + cd.y;
        P.z = P.z * s4.z + cn.z; Q.z = Q.z * s4.z + cd.z;
        P.w = P.w * s4.w + cn.w; Q.w = Q.w * s4.w + cd.w;
    }
    float4 m;
    float r0 = pre.x + P.x / Q.x; m.x = (r0 > 0.f ? r0 : 0.f) + x4.x;
    float r1 = pre.y + P.y / Q.y; m.y = (r1 > 0.f ? r1 : 0.f) + x4.y;
    float r2 = pre.z + P.z / Q.z; m.z = (r2 > 0.f ? r2 : 0.f) + x4.z;
    float r3 = pre.w + P.w / Q.w; m.w = (r3 > 0.f ? r3 : 0.f) + x4.w;
    *(float4*)(g_mixedT + idx4) = m;
    *(float4*)(g_preact + idx4) = make_float4(0.f, 0.f, 0.f, 0.f);
}

// fc1 split-K GEMM: 64x64 tile, 256 threads, double buffered, REDG epilogue
__global__ __launch_bounds__(256) void k_gemm1(const float* __restrict__ W) {
    __shared__ __align__(16) float sA[2][16][68];
    __shared__ __align__(16) float sX[2][16][68];
    const int tid = threadIdx.x;
    const int rb = blockIdx.x * 64;
    const int kb = blockIdx.y * 128;
    int ke = kb + 128; if (ke > NN) ke = NN;
    const int niter = (ke - kb + 15) >> 4;

    const int tx = tid & 15;
    const int ty = tid >> 4;
    const int lr = tid >> 2;          // A row 0..63
    const int lk = (tid & 3) << 2;    // A k 0,4,8,12
    const int xb = (tid & 15) << 2;   // X b col
    const int xk = tid >> 4;          // X k row 0..15

    float acc[4][4];
#pragma unroll
    for (int i = 0; i < 4; i++)
#pragma unroll
        for (int j = 0; j < 4; j++) acc[i][j] = 0.f;

    auto ldA = [&](int k0) -> float4 {
        int kk = k0 + lk;
        if (kk + 4 <= ke) return *(const float4*)(W + (size_t)(rb + lr) * NN + kk);
        float4 v = make_float4(0.f, 0.f, 0.f, 0.f);
        float* pv = &v.x;
#pragma unroll
        for (int j = 0; j < 4; j++)
            if (kk + j < ke) pv[j] = W[(size_t)(rb + lr) * NN + kk + j];
        return v;
    };
    auto ldX = [&](int k0) -> float4 {
        int kk = k0 + xk;
        if (kk < ke) return *(const float4*)(g_mixedT + (size_t)kk * BB + xb);
        return make_float4(0.f, 0.f, 0.f, 0.f);
    };
    auto sts = [&](int buf, float4 a, float4 x) {
        sA[buf][lk + 0][lr] = a.x; sA[buf][lk + 1][lr] = a.y;
        sA[buf][lk + 2][lr] = a.z; sA[buf][lk + 3][lr] = a.w;
        *(float4*)&sX[buf][xk][xb] = x;
    };

    float4 pa = ldA(kb), px = ldX(kb);
    sts(0, pa, px);
    __syncthreads();
    int buf = 0;
    for (int it = 0; it < niter; ++it) {
        float4 na, nx;
        bool more = (it + 1 < niter);
        if (more) { int k0n = kb + (it + 1) * 16; na = ldA(k0n); nx = ldX(k0n); }
#pragma unroll
        for (int kk = 0; kk < 16; kk++) {
            float4 a = *(const float4*)&sA[buf][kk][ty * 4];
            float4 x = *(const float4*)&sX[buf][kk][tx * 4];
            acc[0][0] += a.x * x.x; acc[0][1] += a.x * x.y; acc[0][2] += a.x * x.z; acc[0][3] += a.x * x.w;
            acc[1][0] += a.y * x.x; acc[1][1] += a.y * x.y; acc[1][2] += a.y * x.z; acc[1][3] += a.y * x.w;
            acc[2][0] += a.z * x.x; acc[2][1] += a.z * x.y; acc[2][2] += a.z * x.z; acc[2][3] += a.z * x.w;
            acc[3][0] += a.w * x.x; acc[3][1] += a.w * x.y; acc[3][2] += a.w * x.z; acc[3][3] += a.w * x.w;
        }
        if (more) {
            sts(buf ^ 1, na, nx);
            __syncthreads();
            buf ^= 1;
        }
    }
#pragma unroll
    for (int i = 0; i < 4; i++) {
        int rr = rb + ty * 4 + i;
#pragma unroll
        for (int j = 0; j < 4; j++)
            atomicAdd(&g_hpre[(size_t)rr * BB + tx * 4 + j], acc[i][j]);
    }
}

// bias + tanh -> hT; re-zero hpre
__global__ __launch_bounds__(256) void k_hid(const float* __restrict__ b1) {
    int idx4 = (blockIdx.x * 256 + threadIdx.x) * 4;   // 32*256*4 == EMBED*BB
    int e = idx4 >> 6;
    float bb = b1[e];
    float4 v = *(float4*)(g_hpre + idx4);
    float4 h;
    h.x = tanhf(v.x + bb); h.y = tanhf(v.y + bb);
    h.z = tanhf(v.z + bb); h.w = tanhf(v.w + bb);
    *(float4*)(g_hT + idx4) = h;
    *(float4*)(g_hpre + idx4) = make_float4(0.f, 0.f, 0.f, 0.f);
}

// logits[b][l] = sum_e w2[l][e] * hT[e][b] + b2[l]
__global__ void k_logits(const float* __restrict__ w2, const float* __restrict__ b2,
                         float* __restrict__ out) {
    int l = blockIdx.x;
    int t = threadIdx.x;
    int b = t & 63, q = t >> 6;
    const float* wr = w2 + l * EMBED + q * 128;
    const float* hp = g_hT + (q * 128) * BB + b;
    float acc = 0.f;
#pragma unroll 8
    for (int e = 0; e < 128; e++) acc += wr[e] * hp[e * BB];
    __shared__ float s[256];
    s[t] = acc;
    __syncthreads();
    if (q == 0)
        out[b * LABELS + l] = s[b] + s[64 + b] + s[128 + b] + s[192 + b] + b2[l];
}

extern "C" void kernel_launch(void* const* d_in, const int* in_sizes, int n_in,
                              void* d_out, int out_size) {
    const float* feature    = (const float*)d_in[0];
    const float* init_graph = (const float*)d_in[1];
    const float* theta_w    = (const float*)d_in[2];
    const float* theta_b    = (const float*)d_in[3];
    const float* phi_w      = (const float*)d_in[4];
    /* phi_b cancels in the softmax */
    const float* fc1_w      = (const float*)d_in[6];
    const float* fc1_b      = (const float*)d_in[7];
    const float* fc2_w      = (const float*)d_in[8];
    const float* fc2_b      = (const float*)d_in[9];
    float* out = (float*)d_out;

    cudaFuncSetAttribute(k_main, cudaFuncAttributeMaxDynamicSharedMemorySize, DSMEM);

    k_main<<<G0_BLOCKS + 64 + 126, 256, DSMEM>>>(init_graph, feature, theta_w, theta_b, phi_w);
    k_mix<<<125, 256>>>();
    k_gemm1<<<dim3(8, 16), 256>>>(fc1_w);
    k_hid<<<32, 256>>>(fc1_b);
    k_logits<<<LABELS, 256>>>(fc2_w, fc2_b, out);
}

// round 7
// speedup vs baseline: 1.0654x; 1.0654x over previous
#include <cuda_runtime.h>
#include <cuda_bf16.h>
#include <math.h>
#include <stdint.h>

#define NN 2000
#define BB 64
#define EMBED 512
#define LABELS 20
#define NC 31            // Taylor degree 30
#define NBLK 148

// smem per gemm buffer: 4 tiles (Ahi,Alo,Bhi,Blo) of 64 rows x 72 bf16
#define A_PAD 72
#define TILEB (64 * A_PAD * 2)       // 9216
#define OFF_ALO TILEB
#define OFF_BHI (2 * TILEB)
#define OFF_BLO (3 * TILEB)
#define BUF_STRIDE (4 * TILEB)       // 36864
#define DSMEM 118784                 // > 113.6KB forces 1 CTA/SM -> all 148 resident

// ---- scratch ----
__device__ float g_mixed[BB * NN];        // [b][n]
__device__ float g_part1[4 * NN * BB];    // gemm0 split partials [sp][n][b]
__device__ float g_part2[16 * EMBED * BB];
__device__ float g_hT[EMBED * BB];        // [e][b]
__device__ float g_cn[NC][BB];
__device__ float g_cd[NC][BB];
__device__ float g_alpha, g_gamma;
__device__ unsigned g_epoch, g_count;     // grid barrier (monotonic epoch)

__device__ __forceinline__ void gsync(unsigned base, unsigned k) {
    __syncthreads();
    if (threadIdx.x == 0) {
        __threadfence();
        unsigned t = atomicAdd(&g_count, 1u);
        if (t == NBLK - 1) {
            g_count = 0;
            __threadfence();
            atomicAdd(&g_epoch, 1u);
        } else {
            while (*(volatile unsigned*)&g_epoch - base < k) { __nanosleep(64); }
        }
        __threadfence();
    }
    __syncthreads();
}

__device__ __forceinline__ void mma16816(float* d, const uint32_t* a, const uint32_t* b) {
    asm volatile(
        "mma.sync.aligned.m16n8k16.row.col.f32.bf16.bf16.f32 "
        "{%0,%1,%2,%3}, {%4,%5,%6,%7}, {%8,%9}, {%0,%1,%2,%3};\n"
        : "+f"(d[0]), "+f"(d[1]), "+f"(d[2]), "+f"(d[3])
        : "r"(a[0]), "r"(a[1]), "r"(a[2]), "r"(a[3]), "r"(b[0]), "r"(b[1]));
}

__device__ __forceinline__ void split_store(char* hi, char* lo, int byte, float4 v) {
    __nv_bfloat16 hx = __float2bfloat16(v.x), hy = __float2bfloat16(v.y);
    __nv_bfloat16 hz = __float2bfloat16(v.z), hw = __float2bfloat16(v.w);
    float lx = v.x - __bfloat162float(hx), ly = v.y - __bfloat162float(hy);
    float lz = v.z - __bfloat162float(hz), lw = v.w - __bfloat162float(hw);
    uint2 h2, l2;
    h2.x = (unsigned)__bfloat16_as_ushort(hx) | ((unsigned)__bfloat16_as_ushort(hy) << 16);
    h2.y = (unsigned)__bfloat16_as_ushort(hz) | ((unsigned)__bfloat16_as_ushort(hw) << 16);
    __nv_bfloat16 ax = __float2bfloat16(lx), ay = __float2bfloat16(ly);
    __nv_bfloat16 az = __float2bfloat16(lz), aw = __float2bfloat16(lw);
    l2.x = (unsigned)__bfloat16_as_ushort(ax) | ((unsigned)__bfloat16_as_ushort(ay) << 16);
    l2.y = (unsigned)__bfloat16_as_ushort(az) | ((unsigned)__bfloat16_as_ushort(aw) << 16);
    *(uint2*)(hi + byte) = h2;
    *(uint2*)(lo + byte) = l2;
}

// 64x64 output tile, K window [kb,ke) in chunks of 64, bf16-split 3-mma, fp32 acc.
// A: [nrows x NN] row-major. Bmat: 64 rows x NN row-major (row = output col b).
// dst: partial buffer [n][b] (64 floats per row), rows guarded by nrows.
__device__ __forceinline__ void gemm_tile(
    const float* __restrict__ A, const float* __restrict__ Bmat,
    float* __restrict__ dst, int nrows, int rb, int kb, int ke,
    char* dsm, int tid)
{
    const int wid = tid >> 5, lane = tid & 31;
    const int warp_m = wid >> 2, warp_n = wid & 3;
    const int g = lane >> 2, tig = lane & 3;
    const int rr = tid >> 2;                 // tile row 0..63 (A) / b (B)
    const int q4 = (tid & 3) * 16;           // k sub-offset
    const bool rok = (rb + rr) < nrows;
    const float* arow = A + (size_t)(rb + rr) * NN;
    const float* brow = Bmat + (size_t)rr * NN;
    const int nc = (ke - kb + 63) >> 6;

    float acc[2][2][4];
#pragma unroll
    for (int t = 0; t < 2; t++)
#pragma unroll
        for (int u = 0; u < 2; u++)
#pragma unroll
            for (int j = 0; j < 4; j++) acc[t][u][j] = 0.f;

    float4 ra[4], rbv[4];
    auto ldg_chunk = [&](int c) {
        int m0 = kb + c * 64;
        int mlen = ke - m0; if (mlen > 64) mlen = 64;
#pragma unroll
        for (int i = 0; i < 4; i++) {
            int kk = q4 + i * 4;
            bool ok = (kk + 4 <= mlen);      // kb, mlen multiples of 4
            ra[i] = (rok && ok) ? *(const float4*)(arow + m0 + kk)
                                : make_float4(0.f, 0.f, 0.f, 0.f);
            rbv[i] = ok ? *(const float4*)(brow + m0 + kk)
                        : make_float4(0.f, 0.f, 0.f, 0.f);
        }
    };
    auto cvt_store = [&](int p) {
        char* base = dsm + p * BUF_STRIDE;
#pragma unroll
        for (int i = 0; i < 4; i++) {
            int kk = q4 + i * 4;
            split_store(base, base + OFF_ALO, rr * (A_PAD * 2) + kk * 2, ra[i]);
            split_store(base + OFF_BHI, base + OFF_BLO, rr * (A_PAD * 2) + kk * 2, rbv[i]);
        }
    };
    auto compute = [&](int p) {
        char* base = dsm + p * BUF_STRIDE;
        char* Ahi = base;            char* Alo = base + OFF_ALO;
        char* Bhi = base + OFF_BHI;  char* Blo = base + OFF_BLO;
#pragma unroll
        for (int ks = 0; ks < 4; ks++) {
            const int ko = ks * 16;
            uint32_t ah[2][4], al[2][4], bh[2][2], bl[2][2];
#pragma unroll
            for (int t = 0; t < 2; t++) {
                int row = warp_m * 32 + t * 16 + g;
                int o0 = row * (A_PAD * 2) + (ko + tig * 2) * 2;
                int o1 = (row + 8) * (A_PAD * 2) + (ko + tig * 2) * 2;
                ah[t][0] = *(uint32_t*)(Ahi + o0);
                ah[t][1] = *(uint32_t*)(Ahi + o1);
                ah[t][2] = *(uint32_t*)(Ahi + o0 + 16);
                ah[t][3] = *(uint32_t*)(Ahi + o1 + 16);
                al[t][0] = *(uint32_t*)(Alo + o0);
                al[t][1] = *(uint32_t*)(Alo + o1);
                al[t][2] = *(uint32_t*)(Alo + o0 + 16);
                al[t][3] = *(uint32_t*)(Alo + o1 + 16);
            }
#pragma unroll
            for (int u = 0; u < 2; u++) {
                int col = warp_n * 16 + u * 8 + g;
                int o = col * (A_PAD * 2) + (ko + tig * 2) * 2;
                bh[u][0] = *(uint32_t*)(Bhi + o);
                bh[u][1] = *(uint32_t*)(Bhi + o + 16);
                bl[u][0] = *(uint32_t*)(Blo + o);
                bl[u][1] = *(uint32_t*)(Blo + o + 16);
            }
#pragma unroll
            for (int t = 0; t < 2; t++)
#pragma unroll
                for (int u = 0; u < 2; u++) {
                    mma16816(acc[t][u], ah[t], bh[u]);
                    mma16816(acc[t][u], ah[t], bl[u]);
                    mma16816(acc[t][u], al[t], bh[u]);
                }
        }
    };

    ldg_chunk(0);
    for (int c = 0; c < nc; c++) {
        int p = c & 1;
        cvt_store(p);
        if (c + 1 < nc) ldg_chunk(c + 1);
        __syncthreads();
        compute(p);
    }

#pragma unroll
    for (int t = 0; t < 2; t++) {
        int r0 = rb + warp_m * 32 + t * 16 + g;
#pragma unroll
        for (int u = 0; u < 2; u++) {
            int cn = warp_n * 16 + u * 8 + tig * 2;
            if (r0 < nrows)
                *(float2*)(dst + (size_t)r0 * BB + cn) = make_float2(acc[t][u][0], acc[t][u][1]);
            if (r0 + 8 < nrows)
                *(float2*)(dst + (size_t)(r0 + 8) * BB + cn) = make_float2(acc[t][u][2], acc[t][u][3]);
        }
    }
    __syncthreads();   // protect smem before any later phase reuses dsm
}

__global__ __launch_bounds__(256, 1)
void k_fused(const float* __restrict__ IG, const float* __restrict__ feat,
             const float* __restrict__ tw, const float* __restrict__ tb,
             const float* __restrict__ pw, const float* __restrict__ w1,
             const float* __restrict__ b1, const float* __restrict__ w2,
             const float* __restrict__ b2, float* __restrict__ out)
{
    extern __shared__ __align__(16) char dsm[];
    const int bid = blockIdx.x, tid = threadIdx.x;
    unsigned base = 0;
    if (tid == 0) base = *(volatile unsigned*)&g_epoch;

    // ================= P1: gemm0 (blocks 0..127) + moments (128..143) ========
    if (bid < 128) {
        int mt = bid & 31, sp = bid >> 5;
        int kb = sp * 500, ke = kb + 500;
        gemm_tile(IG, feat, g_part1 + (size_t)sp * NN * BB, NN, mt * 64, kb, ke, dsm, tid);
    } else if (bid < 144) {
        if (bid == 128) {
            __shared__ float sa[64], sg[64];
            if (tid < 64) { sa[tid] = tw[tid] * pw[tid]; sg[tid] = tb[tid] * pw[tid]; }
            __syncthreads();
            if (tid == 0) {
                float A = 0.f, G = 0.f;
                for (int i = 0; i < 64; i++) { A += sa[i]; G += sg[i]; }
                g_alpha = A; g_gamma = G;
            }
            __syncthreads();
        }
        __shared__ float red[32][8];
        __shared__ float sM[32];
        for (int ib = 0; ib < 4; ib++) {
            int b = (bid - 128) * 4 + ib;
            const float* xr = feat + (size_t)b * NN;
            float acc[32];
#pragma unroll
            for (int k = 0; k < 32; k++) acc[k] = 0.f;
            for (int m = tid; m < NN; m += 256) {
                float v = xr[m];
                float p = 1.f;
#pragma unroll
                for (int k = 0; k < 32; k++) { acc[k] += p; p *= v; }
            }
#pragma unroll
            for (int k = 0; k < 32; k++) {
#pragma unroll
                for (int off = 16; off > 0; off >>= 1)
                    acc[k] += __shfl_down_sync(0xffffffffu, acc[k], off);
            }
            int lane = tid & 31, warp = tid >> 5;
            if (lane == 0) {
#pragma unroll
                for (int k = 0; k < 32; k++) red[k][warp] = acc[k];
            }
            __syncthreads();
            if (tid < 32) {
                float s = 0.f;
                for (int w = 0; w < 8; w++) s += red[tid][w];
                sM[tid] = s;
            }
            __syncthreads();
            if (tid < NC) {
                int k = tid;
                float fact = 1.f;
                for (int i = 2; i <= k; i++) fact *= (float)i;
                g_cd[k][b] = sM[k] / fact;
                g_cn[k][b] = sM[k + 1] / fact;
            }
            __syncthreads();
        }
    }
    gsync(base, 1);

    // ================= P2: mix -> g_mixed[b][n] ==============================
    {
        __shared__ float xs[64][17];
        __shared__ float ms[16][68];
        for (int tn = bid; tn < 125; tn += NBLK) {
            int n0 = tn * 16;
            {
                int bl = tid >> 2, no = (tid & 3) * 4;
                float4 v = *(const float4*)(feat + (size_t)bl * NN + n0 + no);
                xs[bl][no] = v.x; xs[bl][no + 1] = v.y;
                xs[bl][no + 2] = v.z; xs[bl][no + 3] = v.w;
            }
            __syncthreads();
            {
                int nl = tid >> 4, b4 = (tid & 15) * 4;
                int row = (n0 + nl) * BB + b4;
                float4 pre = *(float4*)(g_part1 + row);
                float4 p1 = *(float4*)(g_part1 + NN * BB + row);
                float4 p2 = *(float4*)(g_part1 + 2 * NN * BB + row);
                float4 p3 = *(float4*)(g_part1 + 3 * NN * BB + row);
                pre.x += p1.x + p2.x + p3.x; pre.y += p1.y + p2.y + p3.y;
                pre.z += p1.z + p2.z + p3.z; pre.w += p1.w + p2.w + p3.w;
                float al = g_alpha, ga = g_gamma;
                float xv0 = xs[b4 + 0][nl], xv1 = xs[b4 + 1][nl];
                float xv2 = xs[b4 + 2][nl], xv3 = xs[b4 + 3][nl];
                float s0 = al * xv0 + ga, s1 = al * xv1 + ga;
                float s2 = al * xv2 + ga, s3 = al * xv3 + ga;
                float4 P = *(float4*)&g_cn[NC - 1][b4];
                float4 Q = *(float4*)&g_cd[NC - 1][b4];
#pragma unroll
                for (int k = NC - 2; k >= 0; k--) {
                    float4 cn = *(float4*)&g_cn[k][b4];
                    float4 cd = *(float4*)&g_cd[k][b4];
                    P.x = P.x * s0 + cn.x; Q.x = Q.x * s0 + cd.x;
                    P.y = P.y * s1 + cn.y; Q.y = Q.y * s1 + cd.y;
                    P.z = P.z * s2 + cn.z; Q.z = Q.z * s2 + cd.z;
                    P.w = P.w * s3 + cn.w; Q.w = Q.w * s3 + cd.w;
                }
                float r0 = pre.x + P.x / Q.x, r1 = pre.y + P.y / Q.y;
                float r2 = pre.z + P.z / Q.z, r3 = pre.w + P.w / Q.w;
                ms[nl][b4 + 0] = (r0 > 0.f ? r0 : 0.f) + xv0;
                ms[nl][b4 + 1] = (r1 > 0.f ? r1 : 0.f) + xv1;
                ms[nl][b4 + 2] = (r2 > 0.f ? r2 : 0.f) + xv2;
                ms[nl][b4 + 3] = (r3 > 0.f ? r3 : 0.f) + xv3;
            }
            __syncthreads();
            {
                int bl = tid >> 2, no = (tid & 3) * 4;
                float4 v = make_float4(ms[no][bl], ms[no + 1][bl], ms[no + 2][bl], ms[no + 3][bl]);
                *(float4*)(g_mixed + (size_t)bl * NN + n0 + no) = v;
            }
            __syncthreads();
        }
    }
    gsync(base, 2);

    // ================= P3: gemm1 (fc1) blocks 0..127 =========================
    if (bid < 128) {
        int mt = bid & 7, sp = bid >> 3;
        int kb = sp * 128, ke = kb + 128; if (ke > NN) ke = NN;
        gemm_tile(w1, g_mixed, g_part2 + (size_t)sp * EMBED * BB, EMBED, mt * 64, kb, ke, dsm, tid);
    }
    gsync(base, 3);

    // ================= P4: reduce + bias + tanh -> hT ========================
    for (int i = bid * 256 + tid; i < EMBED * BB / 4; i += NBLK * 256) {
        int idx4 = i * 4;
        int e = idx4 >> 6;
        float bb1 = b1[e];
        float4 s = make_float4(bb1, bb1, bb1, bb1);
#pragma unroll
        for (int p = 0; p < 16; p++) {
            float4 v = *(float4*)(g_part2 + (size_t)p * EMBED * BB + idx4);
            s.x += v.x; s.y += v.y; s.z += v.z; s.w += v.w;
        }
        float4 h;
        h.x = tanhf(s.x); h.y = tanhf(s.y); h.z = tanhf(s.z); h.w = tanhf(s.w);
        *(float4*)(g_hT + idx4) = h;
    }
    gsync(base, 4);

    // ================= P5: logits (blocks 0..19) =============================
    if (bid < LABELS) {
        __shared__ float sl[256];
        int l = bid;
        int b = tid & 63, q = tid >> 6;
        const float* wr = w2 + l * EMBED + q * 128;
        const float* hp = g_hT + (q * 128) * BB + b;
        float acc = 0.f;
#pragma unroll 8
        for (int e = 0; e < 128; e++) acc += wr[e] * hp[e * BB];
        sl[tid] = acc;
        __syncthreads();
        if (q == 0)
            out[b * LABELS + l] = sl[b] + sl[64 + b] + sl[128 + b] + sl[192 + b] + b2[l];
    }
}

extern "C" void kernel_launch(void* const* d_in, const int* in_sizes, int n_in,
                              void* d_out, int out_size) {
    const float* feature    = (const float*)d_in[0];
    const float* init_graph = (const float*)d_in[1];
    const float* theta_w    = (const float*)d_in[2];
    const float* theta_b    = (const float*)d_in[3];
    const float* phi_w      = (const float*)d_in[4];
    /* phi_b cancels in the softmax */
    const float* fc1_w      = (const float*)d_in[6];
    const float* fc1_b      = (const float*)d_in[7];
    const float* fc2_w      = (const float*)d_in[8];
    const float* fc2_b      = (const float*)d_in[9];
    float* out = (float*)d_out;

    cudaFuncSetAttribute(k_fused, cudaFuncAttributeMaxDynamicSharedMemorySize, DSMEM);
    k_fused<<<NBLK, 256, DSMEM>>>(init_graph, feature, theta_w, theta_b, phi_w,
                                  fc1_w, fc1_b, fc2_w, fc2_b, out);
}